// round 14
// baseline (speedup 1.0000x reference)
#include <cuda_runtime.h>
#include <stdint.h>

// Problem shape is fixed by setup_inputs(): B=64, N=4, H=512, W=512, num=1024.
#define BB 64
#define NPLANES 4
#define HH 512
#define WW 512
#define HWPIX (HH * WW)            // 262144
#define HW4 (HWPIX / 4)            // 65536 float4s per plane
#define WORDS_PER_B (HWPIX / 32)   // 8192
#define CHUNKS 256                 // chunks per batch; chunk = 32 words = 1024 px
#define NUM 1024
#define IDX_ELEMS (BB * NUM * 2)   // 131072 index values
#define PARTS 16                   // sample blocks per batch (64 points each)

// Scratch (no allocations allowed).
__device__ uint32_t g_bits[BB * WORDS_PER_B];    // 2 MiB  packed valid bits
__device__ int      g_chunk[BB * CHUNKS];        // 64 KiB popcount per chunk

// L2 eviction-policy handles (createpolicy + cache_hint form — legal on any
// access width, unlike the bare .L2::evict_* modifiers which this ptxas only
// accepts on 256-bit accesses).
__device__ __forceinline__ uint64_t mk_policy_evict_first() {
    uint64_t p;
    asm("createpolicy.fractional.L2::evict_first.b64 %0, 1.0;" : "=l"(p));
    return p;
}
__device__ __forceinline__ uint64_t mk_policy_evict_last() {
    uint64_t p;
    asm("createpolicy.fractional.L2::evict_last.b64 %0, 1.0;" : "=l"(p));
    return p;
}
__device__ __forceinline__ float4 ldg_stream_f4(const float4* p, uint64_t pol) {
    float4 r;
    asm volatile("ld.global.nc.L2::cache_hint.v4.f32 {%0,%1,%2,%3}, [%4], %5;"
                 : "=f"(r.x), "=f"(r.y), "=f"(r.z), "=f"(r.w) : "l"(p), "l"(pol));
    return r;
}
__device__ __forceinline__ void stg_keep_u32(uint32_t* p, uint32_t v, uint64_t pol) {
    asm volatile("st.global.L2::cache_hint.u32 [%0], %1, %2;"
                 :: "l"(p), "r"(v), "l"(pol) : "memory");
}
__device__ __forceinline__ void stg_keep_s32(int* p, int v, uint64_t pol) {
    asm volatile("st.global.L2::cache_hint.s32 [%0], %1, %2;"
                 :: "l"(p), "r"(v), "l"(pol) : "memory");
}

// ---------------------------------------------------------------------------
// Kernel 1: valid[b,p] = (sum_n masks[b,n,p]) > 0.5, packed 32 pixels/word.
// 4 consecutive pixels/thread via float4 (measured 6.66 TB/s, 84% DRAM — at
// the LTS cap). Mask loads carry an evict_first policy (read-once stream) so
// they recycle their own L2 lines instead of evicting the g_bits/g_chunk
// working set, which is stored with evict_last — keeping kernel 2's random
// reads L2-resident (R12: they went to DRAM, making k_sample occ-invariant).
// ---------------------------------------------------------------------------
__global__ __launch_bounds__(256) void k_mask_bits(const float4* __restrict__ m4) {
    uint64_t pol_f = mk_policy_evict_first();
    uint64_t pol_l = mk_policy_evict_last();
    int gid4 = blockIdx.x * 256 + threadIdx.x;   // float4 index in [0, B*HW/4)
    int b  = gid4 >> 16;                         // (gid4*4) / HWPIX
    int p4 = gid4 & (HW4 - 1);
    const float4* base = m4 + (size_t)b * NPLANES * HW4 + p4;
    float4 a0 = ldg_stream_f4(base, pol_f);
    float4 a1 = ldg_stream_f4(base + HW4, pol_f);
    float4 a2 = ldg_stream_f4(base + 2 * HW4, pol_f);
    float4 a3 = ldg_stream_f4(base + 3 * HW4, pol_f);
    // Keep the exact association order that validated bit-exact.
    float sx = ((a0.x + a1.x) + a2.x) + a3.x;
    float sy = ((a0.y + a1.y) + a2.y) + a3.y;
    float sz = ((a0.z + a1.z) + a2.z) + a3.z;
    float sw = ((a0.w + a1.w) + a2.w) + a3.w;
    unsigned nib = (unsigned)(sx > 0.5f)
                 | ((unsigned)(sy > 0.5f) << 1)
                 | ((unsigned)(sz > 0.5f) << 2)
                 | ((unsigned)(sw > 0.5f) << 3);
    int l = threadIdx.x & 31;
    unsigned v = nib << ((l & 7) * 4);
    v |= __shfl_xor_sync(0xFFFFFFFFu, v, 1);
    v |= __shfl_xor_sync(0xFFFFFFFFu, v, 2);
    v |= __shfl_xor_sync(0xFFFFFFFFu, v, 4);
    if ((l & 7) == 0) stg_keep_u32(&g_bits[gid4 >> 3], v, pol_l);

    // Chunk popcount: block-wide sum of per-thread nibble popcounts.
    __shared__ int wsum[8];
    int c4 = __popc(nib);
#pragma unroll
    for (int off = 16; off; off >>= 1)
        c4 += __shfl_xor_sync(0xFFFFFFFFu, c4, off);
    if (l == 0) wsum[threadIdx.x >> 5] = c4;
    __syncthreads();
    if (threadIdx.x == 0) {
        int s = 0;
#pragma unroll
        for (int i = 0; i < 8; i++) s += wsum[i];
        stg_keep_s32(&g_chunk[blockIdx.x], s, pol_l);  // blockIdx.x = b*CHUNKS+chunk
    }
}

// ---------------------------------------------------------------------------
// Kernel 2: sampling. PARTS=16 blocks per batch. All 256 threads run the
// cheap redundant prologue (1 KB chunk-count load + shuffle scan); threads
// 0..63 each resolve ONE point: 8-level shared binary search to the chunk,
// one 128 B bit load (now L2-resident), flagged popcount select.
// Replicates: r = min(int(u*float(cnt)), cnt-1); pos = searchsorted(csum, r+1).
// ---------------------------------------------------------------------------
__global__ __launch_bounds__(256) void k_sample(const float* __restrict__ rand_u,
                                                float* __restrict__ out,
                                                int tail_n) {
    __shared__ int s_coarse[CHUNKS];     // exclusive csum of chunk counts
    __shared__ int warp_tot[8];
    __shared__ int s_total;
    int b    = blockIdx.x >> 4;          // batch
    int part = blockIdx.x & (PARTS - 1);
    int t = threadIdx.x;
    int lane = t & 31, wid = t >> 5;

    // Prologue: scan 256 chunk counts (one per thread).
    int c = g_chunk[b * CHUNKS + t];
    int v = c;
#pragma unroll
    for (int off = 1; off < 32; off <<= 1) {
        int n = __shfl_up_sync(0xFFFFFFFFu, v, off);
        if (lane >= off) v += n;
    }
    if (lane == 31) warp_tot[wid] = v;
    __syncthreads();
    int wbase = 0;
#pragma unroll
    for (int i = 0; i < 8; i++) wbase += (i < wid) ? warp_tot[i] : 0;
    s_coarse[t] = wbase + v - c;         // bits strictly before chunk t
    if (t == 255) s_total = wbase + v;   // batch total
    __syncthreads();

    // Tail fill ((H, W) tuple leaves flattened into d_out).
    if (blockIdx.x == 0) {
        for (int i = t; i < tail_n; i += 256) out[IDX_ELEMS + i] = 512.0f;
    }

    if (t >= NUM / PARTS) return;        // threads 64..255 done

    int total = s_total;
    int pt = part * (NUM / PARTS) + t;
    float u = rand_u[b * NUM + pt];

    int pos;
    if (total == 0) {
        // reference: cnt = max(total,1) = 1, r = 0, searchsorted over
        // all-zero csum for target 1 -> insertion point HW.
        pos = HWPIX;
    } else {
        int cnt = total;
        int r = (int)(u * (float)cnt);       // fp32 RN mul, trunc — matches jnp
        if (r > cnt - 1) r = cnt - 1;
        int tgt = r + 1;                     // want the tgt-th set bit (1-indexed)

        // Coarse: last chunk with (bits before chunk) < tgt. s_coarse[0]=0<tgt.
        int lo = 0, hi = CHUNKS;
#pragma unroll
        for (int s = 0; s < 8; s++) {
            int mid = (lo + hi) >> 1;
            if (s_coarse[mid] < tgt) lo = mid; else hi = mid;
        }
        int k = tgt - s_coarse[lo];          // k-th set bit within chunk, k>=1

        // Load the chunk's 32 bit-words (128 B, MLP=8, L2-resident).
        const uint4* bw = reinterpret_cast<const uint4*>(
            g_bits + (size_t)b * WORDS_PER_B + lo * 32);
        int gi = 0;
        bool found = false;
#pragma unroll
        for (int i = 0; i < 8; i++) {
            uint4 q = bw[i];
            int gs = __popc(q.x) + __popc(q.y) + __popc(q.z) + __popc(q.w);
            if (!found) {
                if (k > gs) k -= gs;
                else { gi = i; found = true; }
            }
        }
        uint4 qq = bw[gi];                   // re-load: L1 hit
        int w2 = 0;
        uint32_t wrd = qq.x;
        int pc = __popc(qq.x);
        if (k > pc) {
            k -= pc; wrd = qq.y; w2 = 1; pc = __popc(qq.y);
            if (k > pc) {
                k -= pc; wrd = qq.z; w2 = 2; pc = __popc(qq.z);
                if (k > pc) { k -= pc; wrd = qq.w; w2 = 3; }
            }
        }
        // Fixed-depth 5-step binary select of the k-th set bit (1-indexed).
        int idx = 0;
        int cc = __popc(wrd & 0xFFFFu);
        if (k > cc) { k -= cc; idx += 16; wrd >>= 16; }
        cc = __popc(wrd & 0xFFu);
        if (k > cc) { k -= cc; idx += 8; wrd >>= 8; }
        cc = __popc(wrd & 0xFu);
        if (k > cc) { k -= cc; idx += 4; wrd >>= 4; }
        cc = __popc(wrd & 0x3u);
        if (k > cc) { k -= cc; idx += 2; wrd >>= 2; }
        cc = wrd & 1u;
        if (k > cc) { idx += 1; }
        pos = lo * 1024 + (gi * 4 + w2) * 32 + idx;
    }

    float2 hw;
    hw.x = (float)(pos / WW);
    hw.y = (float)(pos & (WW - 1));
    *reinterpret_cast<float2*>(out + ((size_t)b * NUM + pt) * 2) = hw;
}

extern "C" void kernel_launch(void* const* d_in, const int* in_sizes, int n_in,
                              void* d_out, int out_size) {
    // Identify inputs by size, robust to metadata ordering.
    const float* masks  = nullptr;   // [64,4,512,512] f32 -> 67,108,864 elems
    const float* rand_u = nullptr;   // [64,1024] f32      -> 65,536 elems
    for (int i = 0; i < n_in; i++) {
        if (in_sizes[i] == BB * NPLANES * HWPIX) masks = (const float*)d_in[i];
        else if (in_sizes[i] == BB * NUM)        rand_u = (const float*)d_in[i];
    }
    if (!masks)  masks  = (const float*)d_in[0];
    if (!rand_u) rand_u = (const float*)d_in[1];
    float* out = (float*)d_out;      // [64,1024,2] stored as float32 (+ tail)

    int tail_n = out_size - IDX_ELEMS;
    if (tail_n < 0) tail_n = 0;

    k_mask_bits<<<(BB * HW4) / 256, 256>>>(reinterpret_cast<const float4*>(masks));
    k_sample<<<BB * PARTS, 256>>>(rand_u, out, tail_n);
}

// round 15
// speedup vs baseline: 1.0136x; 1.0136x over previous
#include <cuda_runtime.h>
#include <stdint.h>

// Problem shape is fixed by setup_inputs(): B=64, N=4, H=512, W=512, num=1024.
#define BB 64
#define NPLANES 4
#define HH 512
#define WW 512
#define HWPIX (HH * WW)            // 262144
#define HW4 (HWPIX / 4)            // 65536 float4s per plane
#define WORDS_PER_B (HWPIX / 32)   // 8192
#define CHUNKS 256                 // chunks per batch; chunk = 32 words = 1024 px
#define NUM 1024
#define IDX_ELEMS (BB * NUM * 2)   // 131072 index values
#define PARTS 4                    // sample blocks per batch (256 points each)

// Scratch (no allocations allowed).
__device__ uint32_t g_bits[BB * WORDS_PER_B];    // 2 MiB  packed valid bits
__device__ int      g_chunk[BB * CHUNKS];        // 64 KiB popcount per chunk

// ---------------------------------------------------------------------------
// Kernel 1: valid[b,p] = (sum_n masks[b,n,p]) > 0.5, packed 32 pixels/word.
// 8 consecutive-ish pixels per thread: TWO float4s per plane = 8 independent
// LDG.128 (MLP=8, up from 4) and half the blocks (8192). Plain loads/stores —
// R14 proved L2 policies hurt. Each block covers exactly 2 chunks (2048 px)
// and emits both chunk popcounts.
// ---------------------------------------------------------------------------
__global__ __launch_bounds__(256) void k_mask_bits(const float4* __restrict__ m4) {
    int t = threadIdx.x;
    int l = t & 31;
    int gid4a = blockIdx.x * 512 + t;            // first float4 (chunk A)
    int gid4b = gid4a + 256;                     // second float4 (chunk B)
    int b   = gid4a >> 16;                       // same batch for both halves
    int p4a = gid4a & (HW4 - 1);
    const float4* base = m4 + (size_t)b * NPLANES * HW4 + p4a;
    // 8 independent 16B loads, issued before any arithmetic.
    float4 a0 = base[0];
    float4 a1 = base[HW4];
    float4 a2 = base[2 * HW4];
    float4 a3 = base[3 * HW4];
    float4 b0 = base[256];
    float4 b1 = base[HW4 + 256];
    float4 b2 = base[2 * HW4 + 256];
    float4 b3 = base[3 * HW4 + 256];
    // Keep the exact association order that validated bit-exact.
    float sax = ((a0.x + a1.x) + a2.x) + a3.x;
    float say = ((a0.y + a1.y) + a2.y) + a3.y;
    float saz = ((a0.z + a1.z) + a2.z) + a3.z;
    float saw = ((a0.w + a1.w) + a2.w) + a3.w;
    float sbx = ((b0.x + b1.x) + b2.x) + b3.x;
    float sby = ((b0.y + b1.y) + b2.y) + b3.y;
    float sbz = ((b0.z + b1.z) + b2.z) + b3.z;
    float sbw = ((b0.w + b1.w) + b2.w) + b3.w;
    unsigned nibA = (unsigned)(sax > 0.5f)
                  | ((unsigned)(say > 0.5f) << 1)
                  | ((unsigned)(saz > 0.5f) << 2)
                  | ((unsigned)(saw > 0.5f) << 3);
    unsigned nibB = (unsigned)(sbx > 0.5f)
                  | ((unsigned)(sby > 0.5f) << 1)
                  | ((unsigned)(sbz > 0.5f) << 2)
                  | ((unsigned)(sbw > 0.5f) << 3);
    // Pack 8 nibbles -> one 32-bit word per 8-lane group (pixel-order bits).
    unsigned vA = nibA << ((l & 7) * 4);
    unsigned vB = nibB << ((l & 7) * 4);
    vA |= __shfl_xor_sync(0xFFFFFFFFu, vA, 1);
    vB |= __shfl_xor_sync(0xFFFFFFFFu, vB, 1);
    vA |= __shfl_xor_sync(0xFFFFFFFFu, vA, 2);
    vB |= __shfl_xor_sync(0xFFFFFFFFu, vB, 2);
    vA |= __shfl_xor_sync(0xFFFFFFFFu, vA, 4);
    vB |= __shfl_xor_sync(0xFFFFFFFFu, vB, 4);
    if ((l & 7) == 0) {
        g_bits[gid4a >> 3] = vA;                 // word = (4*gid4)/32
        g_bits[gid4b >> 3] = vB;
    }

    // Chunk popcounts: block-wide sums of per-thread nibble popcounts.
    __shared__ int wsumA[8], wsumB[8];
    int cA = __popc(nibA);
    int cB = __popc(nibB);
#pragma unroll
    for (int off = 16; off; off >>= 1) {
        cA += __shfl_xor_sync(0xFFFFFFFFu, cA, off);
        cB += __shfl_xor_sync(0xFFFFFFFFu, cB, off);
    }
    if (l == 0) { wsumA[t >> 5] = cA; wsumB[t >> 5] = cB; }
    __syncthreads();
    if (t == 0) {
        int sA = 0, sB = 0;
#pragma unroll
        for (int i = 0; i < 8; i++) { sA += wsumA[i]; sB += wsumB[i]; }
        g_chunk[blockIdx.x * 2]     = sA;        // chunk index = px/1024
        g_chunk[blockIdx.x * 2 + 1] = sB;
    }
}

// ---------------------------------------------------------------------------
// Kernel 2: sampling — byte-for-byte the R10 form (best measured: 47.6 us
// total). PARTS=4 blocks per batch, ONE point per thread. Prologue: load the
// 256 chunk counts, warp-shuffle scan -> coarse csum in shared. Per point:
// 8-level shared binary search to the chunk, one 128 B bit load (MLP=8),
// flagged popcount select.
// Replicates: r = min(int(u*float(cnt)), cnt-1); pos = searchsorted(csum, r+1).
// ---------------------------------------------------------------------------
__global__ __launch_bounds__(256) void k_sample(const float* __restrict__ rand_u,
                                                float* __restrict__ out,
                                                int tail_n) {
    __shared__ int s_coarse[CHUNKS];     // exclusive csum of chunk counts
    __shared__ int warp_tot[8];
    __shared__ int s_total;
    int b    = blockIdx.x >> 2;          // batch
    int part = blockIdx.x & (PARTS - 1);
    int t = threadIdx.x;
    int lane = t & 31, wid = t >> 5;

    // Prologue: scan 256 chunk counts (one per thread).
    int c = g_chunk[b * CHUNKS + t];
    int v = c;
#pragma unroll
    for (int off = 1; off < 32; off <<= 1) {
        int n = __shfl_up_sync(0xFFFFFFFFu, v, off);
        if (lane >= off) v += n;
    }
    if (lane == 31) warp_tot[wid] = v;
    __syncthreads();
    int wbase = 0;
#pragma unroll
    for (int i = 0; i < 8; i++) wbase += (i < wid) ? warp_tot[i] : 0;
    s_coarse[t] = wbase + v - c;         // bits strictly before chunk t
    if (t == 255) s_total = wbase + v;   // batch total
    __syncthreads();

    // Tail fill ((H, W) tuple leaves flattened into d_out).
    if (blockIdx.x == 0) {
        for (int i = t; i < tail_n; i += 256) out[IDX_ELEMS + i] = 512.0f;
    }

    int total = s_total;
    int pt = part * 256 + t;
    float u = rand_u[b * NUM + pt];

    int pos;
    if (total == 0) {
        // reference: cnt = max(total,1) = 1, r = 0, searchsorted over
        // all-zero csum for target 1 -> insertion point HW.
        pos = HWPIX;
    } else {
        int cnt = total;
        int r = (int)(u * (float)cnt);       // fp32 RN mul, trunc — matches jnp
        if (r > cnt - 1) r = cnt - 1;
        int tgt = r + 1;                     // want the tgt-th set bit (1-indexed)

        // Coarse: last chunk with (bits before chunk) < tgt. s_coarse[0]=0<tgt.
        int lo = 0, hi = CHUNKS;
#pragma unroll
        for (int s = 0; s < 8; s++) {
            int mid = (lo + hi) >> 1;
            if (s_coarse[mid] < tgt) lo = mid; else hi = mid;
        }
        int k = tgt - s_coarse[lo];          // k-th set bit within chunk, k>=1

        // Load the chunk's 32 bit-words (128 B, MLP=8) and select the word.
        const uint4* bw = reinterpret_cast<const uint4*>(
            g_bits + (size_t)b * WORDS_PER_B + lo * 32);
        int gi = 0;
        bool found = false;
#pragma unroll
        for (int i = 0; i < 8; i++) {
            uint4 q = bw[i];
            int gs = __popc(q.x) + __popc(q.y) + __popc(q.z) + __popc(q.w);
            if (!found) {
                if (k > gs) k -= gs;
                else { gi = i; found = true; }
            }
        }
        uint4 qq = bw[gi];                   // re-load: L1 hit
        int w2 = 0;
        uint32_t wrd = qq.x;
        int pc = __popc(qq.x);
        if (k > pc) {
            k -= pc; wrd = qq.y; w2 = 1; pc = __popc(qq.y);
            if (k > pc) {
                k -= pc; wrd = qq.z; w2 = 2; pc = __popc(qq.z);
                if (k > pc) { k -= pc; wrd = qq.w; w2 = 3; }
            }
        }
        // Fixed-depth 5-step binary select of the k-th set bit (1-indexed).
        int idx = 0;
        int cc = __popc(wrd & 0xFFFFu);
        if (k > cc) { k -= cc; idx += 16; wrd >>= 16; }
        cc = __popc(wrd & 0xFFu);
        if (k > cc) { k -= cc; idx += 8; wrd >>= 8; }
        cc = __popc(wrd & 0xFu);
        if (k > cc) { k -= cc; idx += 4; wrd >>= 4; }
        cc = __popc(wrd & 0x3u);
        if (k > cc) { k -= cc; idx += 2; wrd >>= 2; }
        cc = wrd & 1u;
        if (k > cc) { idx += 1; }
        pos = lo * 1024 + (gi * 4 + w2) * 32 + idx;
    }

    float2 hw;
    hw.x = (float)(pos / WW);
    hw.y = (float)(pos & (WW - 1));
    *reinterpret_cast<float2*>(out + ((size_t)b * NUM + pt) * 2) = hw;
}

extern "C" void kernel_launch(void* const* d_in, const int* in_sizes, int n_in,
                              void* d_out, int out_size) {
    // Identify inputs by size, robust to metadata ordering.
    const float* masks  = nullptr;   // [64,4,512,512] f32 -> 67,108,864 elems
    const float* rand_u = nullptr;   // [64,1024] f32      -> 65,536 elems
    for (int i = 0; i < n_in; i++) {
        if (in_sizes[i] == BB * NPLANES * HWPIX) masks = (const float*)d_in[i];
        else if (in_sizes[i] == BB * NUM)        rand_u = (const float*)d_in[i];
    }
    if (!masks)  masks  = (const float*)d_in[0];
    if (!rand_u) rand_u = (const float*)d_in[1];
    float* out = (float*)d_out;      // [64,1024,2] stored as float32 (+ tail)

    int tail_n = out_size - IDX_ELEMS;
    if (tail_n < 0) tail_n = 0;

    k_mask_bits<<<(BB * HW4) / 512, 256>>>(reinterpret_cast<const float4*>(masks));
    k_sample<<<BB * PARTS, 256>>>(rand_u, out, tail_n);
}

// round 16
// speedup vs baseline: 1.0491x; 1.0350x over previous
#include <cuda_runtime.h>
#include <stdint.h>

// Problem shape is fixed by setup_inputs(): B=64, N=4, H=512, W=512, num=1024.
#define BB 64
#define NPLANES 4
#define HH 512
#define WW 512
#define HWPIX (HH * WW)            // 262144
#define HW4 (HWPIX / 4)            // 65536 float4s per plane
#define WORDS_PER_B (HWPIX / 32)   // 8192
#define CHUNKS 256                 // chunks per batch; chunk = 32 words = 1024 px
#define NUM 1024
#define IDX_ELEMS (BB * NUM * 2)   // 131072 index values
#define PARTS 4                    // sample blocks per batch (256 points each)

// Scratch (no allocations allowed).
__device__ uint32_t g_bits[BB * WORDS_PER_B];    // 2 MiB  packed valid bits
__device__ int      g_chunk[BB * CHUNKS];        // 64 KiB popcount per chunk

// ---------------------------------------------------------------------------
// Kernel 1: valid[b,p] = (sum_n masks[b,n,p]) > 0.5, packed 32 pixels/word.
// Byte-for-byte the R10 form (measured 41.2 us, 84% DRAM, 6.66 TB/s — at the
// LTS cap; MLP=8 and L2 policies both regressed it). Adds only a PDL trigger
// so kernel 2 can launch while this kernel drains.
// ---------------------------------------------------------------------------
__global__ __launch_bounds__(256) void k_mask_bits(const float4* __restrict__ m4) {
    int gid4 = blockIdx.x * 256 + threadIdx.x;   // float4 index in [0, B*HW/4)
    int b  = gid4 >> 16;                         // (gid4*4) / HWPIX
    int p4 = gid4 & (HW4 - 1);
    const float4* base = m4 + (size_t)b * NPLANES * HW4 + p4;
    float4 a0 = base[0];
    float4 a1 = base[HW4];
    float4 a2 = base[2 * HW4];
    float4 a3 = base[3 * HW4];
    // Keep the exact association order that validated bit-exact.
    float sx = ((a0.x + a1.x) + a2.x) + a3.x;
    float sy = ((a0.y + a1.y) + a2.y) + a3.y;
    float sz = ((a0.z + a1.z) + a2.z) + a3.z;
    float sw = ((a0.w + a1.w) + a2.w) + a3.w;
    unsigned nib = (unsigned)(sx > 0.5f)
                 | ((unsigned)(sy > 0.5f) << 1)
                 | ((unsigned)(sz > 0.5f) << 2)
                 | ((unsigned)(sw > 0.5f) << 3);
    int l = threadIdx.x & 31;
    unsigned v = nib << ((l & 7) * 4);
    v |= __shfl_xor_sync(0xFFFFFFFFu, v, 1);
    v |= __shfl_xor_sync(0xFFFFFFFFu, v, 2);
    v |= __shfl_xor_sync(0xFFFFFFFFu, v, 4);
    if ((l & 7) == 0) g_bits[gid4 >> 5 << 2 | (l >> 3) | ((threadIdx.x >> 5) << 2) * 0] = v;

    // NOTE: the line above must be exactly word = gid4/8; keep it simple:
    // (rewritten below to avoid any index confusion)
    if ((l & 7) == 0) g_bits[gid4 >> 3] = v;     // word = (4*gid4)/32

    // Chunk popcount: block-wide sum of per-thread nibble popcounts.
    __shared__ int wsum[8];
    int c4 = __popc(nib);
#pragma unroll
    for (int off = 16; off; off >>= 1)
        c4 += __shfl_xor_sync(0xFFFFFFFFu, c4, off);
    if (l == 0) wsum[threadIdx.x >> 5] = c4;
    __syncthreads();
    if (threadIdx.x == 0) {
        int s = 0;
#pragma unroll
        for (int i = 0; i < 8; i++) s += wsum[i];
        g_chunk[blockIdx.x] = s;                 // blockIdx.x = b*CHUNKS + chunk
    }

    // PDL: this block's useful stores are issued — allow the dependent
    // k_sample launch to begin spinning up while remaining blocks stream.
    cudaTriggerProgrammaticLaunchCompletion();
}

// ---------------------------------------------------------------------------
// Kernel 2: sampling — R10 form (best measured), launched with PDL so its
// launch latency and k1-independent prologue (tail fill + rand_u load, a
// ~600-cycle DRAM hop) overlap with kernel 1's tail. g_chunk/g_bits are only
// touched after cudaGridDependencySynchronize() (full k1 visibility).
// Replicates: r = min(int(u*float(cnt)), cnt-1); pos = searchsorted(csum, r+1).
// ---------------------------------------------------------------------------
__global__ __launch_bounds__(256) void k_sample(const float* __restrict__ rand_u,
                                                float* __restrict__ out,
                                                int tail_n) {
    __shared__ int s_coarse[CHUNKS];     // exclusive csum of chunk counts
    __shared__ int warp_tot[8];
    __shared__ int s_total;
    int b    = blockIdx.x >> 2;          // batch
    int part = blockIdx.x & (PARTS - 1);
    int t = threadIdx.x;
    int lane = t & 31, wid = t >> 5;

    // ---- k1-independent work first (overlaps with k1 under PDL) ----
    // Tail fill ((H, W) tuple leaves flattened into d_out).
    if (blockIdx.x == 0) {
        for (int i = t; i < tail_n; i += 256) out[IDX_ELEMS + i] = 512.0f;
    }
    int pt = part * 256 + t;
    float u = rand_u[b * NUM + pt];      // DRAM hop pulled off the critical path

    // ---- wait for k1's g_bits/g_chunk to be visible ----
    cudaGridDependencySynchronize();

    // Prologue: scan 256 chunk counts (one per thread).
    int c = g_chunk[b * CHUNKS + t];
    int v = c;
#pragma unroll
    for (int off = 1; off < 32; off <<= 1) {
        int n = __shfl_up_sync(0xFFFFFFFFu, v, off);
        if (lane >= off) v += n;
    }
    if (lane == 31) warp_tot[wid] = v;
    __syncthreads();
    int wbase = 0;
#pragma unroll
    for (int i = 0; i < 8; i++) wbase += (i < wid) ? warp_tot[i] : 0;
    s_coarse[t] = wbase + v - c;         // bits strictly before chunk t
    if (t == 255) s_total = wbase + v;   // batch total
    __syncthreads();

    int total = s_total;

    int pos;
    if (total == 0) {
        // reference: cnt = max(total,1) = 1, r = 0, searchsorted over
        // all-zero csum for target 1 -> insertion point HW.
        pos = HWPIX;
    } else {
        int cnt = total;
        int r = (int)(u * (float)cnt);       // fp32 RN mul, trunc — matches jnp
        if (r > cnt - 1) r = cnt - 1;
        int tgt = r + 1;                     // want the tgt-th set bit (1-indexed)

        // Coarse: last chunk with (bits before chunk) < tgt. s_coarse[0]=0<tgt.
        int lo = 0, hi = CHUNKS;
#pragma unroll
        for (int s = 0; s < 8; s++) {
            int mid = (lo + hi) >> 1;
            if (s_coarse[mid] < tgt) lo = mid; else hi = mid;
        }
        int k = tgt - s_coarse[lo];          // k-th set bit within chunk, k>=1

        // Load the chunk's 32 bit-words (128 B, MLP=8) and select the word.
        const uint4* bw = reinterpret_cast<const uint4*>(
            g_bits + (size_t)b * WORDS_PER_B + lo * 32);
        int gi = 0;
        bool found = false;
#pragma unroll
        for (int i = 0; i < 8; i++) {
            uint4 q = bw[i];
            int gs = __popc(q.x) + __popc(q.y) + __popc(q.z) + __popc(q.w);
            if (!found) {
                if (k > gs) k -= gs;
                else { gi = i; found = true; }
            }
        }
        uint4 qq = bw[gi];                   // re-load: L1 hit
        int w2 = 0;
        uint32_t wrd = qq.x;
        int pc = __popc(qq.x);
        if (k > pc) {
            k -= pc; wrd = qq.y; w2 = 1; pc = __popc(qq.y);
            if (k > pc) {
                k -= pc; wrd = qq.z; w2 = 2; pc = __popc(qq.z);
                if (k > pc) { k -= pc; wrd = qq.w; w2 = 3; }
            }
        }
        // Fixed-depth 5-step binary select of the k-th set bit (1-indexed).
        int idx = 0;
        int cc = __popc(wrd & 0xFFFFu);
        if (k > cc) { k -= cc; idx += 16; wrd >>= 16; }
        cc = __popc(wrd & 0xFFu);
        if (k > cc) { k -= cc; idx += 8; wrd >>= 8; }
        cc = __popc(wrd & 0xFu);
        if (k > cc) { k -= cc; idx += 4; wrd >>= 4; }
        cc = __popc(wrd & 0x3u);
        if (k > cc) { k -= cc; idx += 2; wrd >>= 2; }
        cc = wrd & 1u;
        if (k > cc) { idx += 1; }
        pos = lo * 1024 + (gi * 4 + w2) * 32 + idx;
    }

    float2 hw;
    hw.x = (float)(pos / WW);
    hw.y = (float)(pos & (WW - 1));
    *reinterpret_cast<float2*>(out + ((size_t)b * NUM + pt) * 2) = hw;
}

extern "C" void kernel_launch(void* const* d_in, const int* in_sizes, int n_in,
                              void* d_out, int out_size) {
    // Identify inputs by size, robust to metadata ordering.
    const float* masks  = nullptr;   // [64,4,512,512] f32 -> 67,108,864 elems
    const float* rand_u = nullptr;   // [64,1024] f32      -> 65,536 elems
    for (int i = 0; i < n_in; i++) {
        if (in_sizes[i] == BB * NPLANES * HWPIX) masks = (const float*)d_in[i];
        else if (in_sizes[i] == BB * NUM)        rand_u = (const float*)d_in[i];
    }
    if (!masks)  masks  = (const float*)d_in[0];
    if (!rand_u) rand_u = (const float*)d_in[1];
    float* out = (float*)d_out;      // [64,1024,2] stored as float32 (+ tail)

    int tail_n = out_size - IDX_ELEMS;
    if (tail_n < 0) tail_n = 0;

    k_mask_bits<<<(BB * HW4) / 256, 256>>>(reinterpret_cast<const float4*>(masks));

    // k_sample with programmatic dependent launch: overlaps its launch +
    // k1-independent prologue with k1's drain; correctness enforced by
    // cudaGridDependencySynchronize() in the kernel.
    cudaLaunchConfig_t cfg = {};
    cfg.gridDim = dim3(BB * PARTS);
    cfg.blockDim = dim3(256);
    cudaLaunchAttribute attrs[1];
    attrs[0].id = cudaLaunchAttributeProgrammaticStreamSerialization;
    attrs[0].val.programmaticStreamSerializationAllowed = 1;
    cfg.attrs = attrs;
    cfg.numAttrs = 1;
    cudaLaunchKernelEx(&cfg, k_sample, rand_u, out, tail_n);
}